// round 8
// baseline (speedup 1.0000x reference)
#include <cuda_runtime.h>
#include <cuda_fp16.h>
#include <math.h>
#include <stdint.h>

// ---------------------------------------------------------------------------
// DH-SFNN forward via mma.sync fp16 with scaled 2-splits (fp32-equivalent):
//   GEMM1: U = X@Wm1^T  as  xh*wh + xl*wh + (xh*2^-11)*((w-wh)*2^11)   [3 prod]
//   GEMM2: U = S@Wm2^T  as  s*wh + (s*2^-11)*((w-wh)*2^11)             [2 prod]
// R8: 4 warps x (64x64) warp tiles + fragment reuse across products —
// halves LDSM traffic so the smem crossbar stops co-limiting the tensor pipe.
// ---------------------------------------------------------------------------

#define B_    128
#define T_    250
#define IN_   700
#define INP_  704
#define H_    512
#define BR_   4
#define HB_   2048
#define OUT_  20
#define M_    (B_ * T_)    // 32000
#define WARM_ 11

// ---------------- scratch (static device globals) --------------------------
__device__ __half g_Xs [(size_t)3 * M_ * INP_];   // {xh, xl, xh*2^-11}  135 MB
__device__ __half g_W1s[(size_t)2 * HB_ * INP_];  // {wh, wl*2^11}       5.8 MB
__device__ __half g_W2s[(size_t)2 * HB_ * H_];    // {wh, wl*2^11}       4.2 MB
__device__ float  g_U  [(size_t)M_ * HB_];        // drive               262 MB
__device__ __half g_S1 [(size_t)2 * M_ * H_];     // {s, s*2^-11}        65.5 MB
__device__ __half g_S2 [(size_t)M_ * H_];         // layer-2 spikes      32.8 MB
__device__ float  g_Z  [(size_t)M_ * OUT_];

// ---------------- PTX helpers ----------------------------------------------
__device__ __forceinline__ uint32_t smem_u32(const void* p) {
    uint32_t a;
    asm("{ .reg .u64 t; cvta.to.shared.u64 t, %1; cvt.u32.u64 %0, t; }"
        : "=r"(a) : "l"(p));
    return a;
}
__device__ __forceinline__ void ldmatrix_x4(uint32_t* r, uint32_t addr) {
    asm volatile("ldmatrix.sync.aligned.m8n8.x4.shared.b16 {%0,%1,%2,%3}, [%4];"
                 : "=r"(r[0]), "=r"(r[1]), "=r"(r[2]), "=r"(r[3]) : "r"(addr));
}
__device__ __forceinline__ void mma16816(float* c, const uint32_t* a,
                                         uint32_t b0, uint32_t b1) {
    asm volatile(
        "mma.sync.aligned.m16n8k16.row.col.f32.f16.f16.f32 "
        "{%0,%1,%2,%3}, {%4,%5,%6,%7}, {%8,%9}, {%0,%1,%2,%3};"
        : "+f"(c[0]), "+f"(c[1]), "+f"(c[2]), "+f"(c[3])
        : "r"(a[0]), "r"(a[1]), "r"(a[2]), "r"(a[3]), "r"(b0), "r"(b1));
}
__device__ __forceinline__ void cp16(uint32_t dst, const void* src) {
    asm volatile("cp.async.cg.shared.global [%0], [%1], 16;"
                 :: "r"(dst), "l"(src));
}
#define CP_COMMIT() asm volatile("cp.async.commit_group;" ::: "memory")
#define CP_WAIT0()  asm volatile("cp.async.wait_group 0;" ::: "memory")

// ---------------- prep kernels ---------------------------------------------
__global__ void split_x_kernel(const float* __restrict__ x) {
    size_t idx = (size_t)blockIdx.x * blockDim.x + threadIdx.x;
    if (idx >= (size_t)M_ * INP_) return;
    int mm = (int)(idx / INP_), c = (int)(idx % INP_);
    float v = (c < IN_) ? x[(size_t)mm * IN_ + c] : 0.0f;
    __half h  = __float2half_rn(v);
    __half l  = __float2half_rn(v - __half2float(h));
    __half hs = __float2half_rn(__half2float(h) * (1.0f / 2048.0f));
    const size_t P = (size_t)M_ * INP_;
    g_Xs[idx] = h; g_Xs[P + idx] = l; g_Xs[2 * P + idx] = hs;
}

__global__ void split_w1_kernel(const float* __restrict__ W1,
                                const float* __restrict__ mask1) {
    size_t idx = (size_t)blockIdx.x * blockDim.x + threadIdx.x;
    if (idx >= (size_t)HB_ * INP_) return;
    int r = (int)(idx / INP_), c = (int)(idx % INP_);
    float v = (c < IN_) ? W1[(size_t)r * IN_ + c] * mask1[(size_t)r * IN_ + c] : 0.0f;
    __half h  = __float2half_rn(v);
    __half ls = __float2half_rn((v - __half2float(h)) * 2048.0f);
    const size_t P = (size_t)HB_ * INP_;
    g_W1s[idx] = h; g_W1s[P + idx] = ls;
}

__global__ void split_w2_kernel(const float* __restrict__ W2,
                                const float* __restrict__ mask2) {
    size_t idx = (size_t)blockIdx.x * blockDim.x + threadIdx.x;
    if (idx >= (size_t)HB_ * H_) return;
    float v = W2[idx] * mask2[idx];
    __half h  = __float2half_rn(v);
    __half ls = __float2half_rn((v - __half2float(h)) * 2048.0f);
    const size_t P = (size_t)HB_ * H_;
    g_W2s[idx] = h; g_W2s[P + idx] = ls;
}

// ---------------------------------------------------------------------------
// fp16 mma.sync GEMM with scaled splits:  U[128m x 128n] = sum_p A[pa]*B[pb]^T
// CTA 128x128, 4 warps (2m x 2n), warp tile 64x64, K-chunk 32.
// Per kt: load ALL plane fragments once, reuse across products.
// 2-stage cp.async pipeline, one __syncthreads per chunk.
// MODE 0: A planes {xh, xl, xhs}, B {wh, wls}; products (0,0),(1,0),(2,1).
// MODE 1: A planes {s, ss},       B {wh, wls}; products (0,0),(1,1).
// ---------------------------------------------------------------------------
#define TSTRIDE 40
#define TBYTES  (128 * TSTRIDE * 2)      // 10240 B per tile

template <int MODE>
__global__ __launch_bounds__(128, 2)
void gemm_mma(const __half* __restrict__ A0, const __half* __restrict__ A1,
              const __half* __restrict__ A2, const __half* __restrict__ Bw0,
              const __half* __restrict__ Bw1, float* __restrict__ U, int K)
{
    constexpr int NA  = (MODE == 0) ? 3 : 2;
    constexpr int NT  = NA + 2;
    constexpr int NPR = (MODE == 0) ? 3 : 2;
    constexpr int PA_[2][3] = {{0, 1, 2}, {0, 1, 0}};
    constexpr int PB_[2][3] = {{0, 0, 1}, {0, 1, 0}};
    constexpr int STG = NT * TBYTES;     // stage stride in bytes

    extern __shared__ char smem[];
    const uint32_t sb = smem_u32(smem);

    const int tid  = threadIdx.x;
    const int wid  = tid >> 5, lane = tid & 31;
    const int m0   = blockIdx.y * 128, n0 = blockIdx.x * 128;
    const int mw   = (wid >> 1) * 64;    // warp m offset (2 warps in m)
    const int nw   = (wid & 1) * 64;     // warp n offset (2 warps in n)

    const int a_row = lane & 15;
    const int a_kh  = (lane >> 4) << 3;
    const int b_n   = (lane & 7) + ((lane >> 4) << 3);
    const int b_kh  = ((lane >> 3) & 1) << 3;

    // tile source base pointers (row 0, k 0)
    const __half* tp[NT];
    tp[0] = A0 + (size_t)m0 * K;
    tp[1] = A1 + (size_t)m0 * K;
    if (MODE == 0) tp[2] = A2 + (size_t)m0 * K;
    tp[NA]     = Bw0 + (size_t)n0 * K;
    tp[NA + 1] = Bw1 + (size_t)n0 * K;

    // per-thread load coords: 4 x 16B per tile (512 quads / 128 threads)
    const int lq = tid & 3;            // 16B quad in row
    const int lr = tid >> 2;           // row 0..31 (+32/64/96 on later passes)

    float acc[4][8][4];
#pragma unroll
    for (int i = 0; i < 4; i++)
#pragma unroll
        for (int j = 0; j < 8; j++)
#pragma unroll
            for (int q = 0; q < 4; q++) acc[i][j][q] = 0.0f;

    const int nchunk = K >> 5;

    // ---- prologue: stage 0 loads ----
#pragma unroll
    for (int t = 0; t < NT; t++)
#pragma unroll
        for (int j = 0; j < 4; j++) {
            const int r = lr + j * 32;
            cp16(sb + t * TBYTES + (r * TSTRIDE + lq * 8) * 2,
                 tp[t] + (size_t)r * K + lq * 8);
        }
    CP_COMMIT();

    for (int ch = 0; ch < nchunk; ch++) {
        CP_WAIT0();
        __syncthreads();   // stage cur ready; all warps past mma(ch-1)

        // issue loads for chunk ch+1 into the other stage (overlaps MMAs)
        if (ch + 1 < nchunk) {
            const int k1 = (ch + 1) << 5;
            const uint32_t so = ((ch + 1) & 1) * STG;
#pragma unroll
            for (int t = 0; t < NT; t++)
#pragma unroll
                for (int j = 0; j < 4; j++) {
                    const int r = lr + j * 32;
                    cp16(sb + so + t * TBYTES + (r * TSTRIDE + lq * 8) * 2,
                         tp[t] + (size_t)r * K + k1 + lq * 8);
                }
        }
        CP_COMMIT();

        // ---- MMA on stage cur: load every fragment once per kt ----
        const uint32_t cb = sb + (ch & 1) * STG;
#pragma unroll
        for (int kt = 0; kt < 2; kt++) {
            uint32_t af[NA][4][4];
#pragma unroll
            for (int pl = 0; pl < NA; pl++)
#pragma unroll
                for (int mi = 0; mi < 4; mi++)
                    ldmatrix_x4(af[pl][mi],
                        cb + pl * TBYTES
                           + 2u * (uint32_t)((mw + mi * 16 + a_row) * TSTRIDE
                                             + kt * 16 + a_kh));
            uint32_t bf[2][4][4];
#pragma unroll
            for (int pl = 0; pl < 2; pl++)
#pragma unroll
                for (int ng = 0; ng < 4; ng++)
                    ldmatrix_x4(bf[pl][ng],
                        cb + (NA + pl) * TBYTES
                           + 2u * (uint32_t)((nw + ng * 16 + b_n) * TSTRIDE
                                             + kt * 16 + b_kh));
#pragma unroll
            for (int p = 0; p < NPR; p++)
#pragma unroll
                for (int mi = 0; mi < 4; mi++)
#pragma unroll
                    for (int ni = 0; ni < 8; ni++)
                        mma16816(acc[mi][ni], af[PA_[MODE][p]][mi],
                                 bf[PB_[MODE][p]][ni >> 1][(ni & 1) * 2],
                                 bf[PB_[MODE][p]][ni >> 1][(ni & 1) * 2 + 1]);
        }
    }

    // Epilogue: direct global stores (float2), C frag layout m16n8.f32
    const int er = lane >> 2;
    const int ec = (lane & 3) * 2;
#pragma unroll
    for (int mi = 0; mi < 4; mi++) {
#pragma unroll
        for (int ni = 0; ni < 8; ni++) {
            const size_t row = (size_t)(m0 + mw + mi * 16 + er);
            const size_t col = (size_t)(n0 + nw + ni * 8 + ec);
            *(float2*)&U[row * HB_ + col] =
                make_float2(acc[mi][ni][0], acc[mi][ni][1]);
            *(float2*)&U[(row + 8) * HB_ + col] =
                make_float2(acc[mi][ni][2], acc[mi][ni][3]);
        }
    }
}

// ---------------------------------------------------------------------------
// LIF scan (fp32 state). Writes spike plane S; optionally the scaled plane
// Ss = s * 2^-11 (exact in fp16) for the next layer's 2-product GEMM.
// ---------------------------------------------------------------------------
template <int TWO>
__global__ __launch_bounds__(128)
void scan_kernel(const float* __restrict__ U, const float* __restrict__ tau_m,
                 const float* __restrict__ tau_n, const float* __restrict__ bias,
                 __half* __restrict__ S, __half* __restrict__ Ss)
{
    const int idx = blockIdx.x * blockDim.x + threadIdx.x;
    const int b = idx >> 9, h = idx & 511;

    float beta[4], ob[4], bb[4];
#pragma unroll
    for (int j = 0; j < 4; j++) {
        const float tn = tau_n[h * 4 + j];
        beta[j] = 1.0f / (1.0f + expf(-tn));
        ob[j]   = 1.0f - beta[j];
        bb[j]   = bias[h * 4 + j];
    }
    const float alpha = 1.0f / (1.0f + expf(-tau_m[h]));
    const float oa    = 1.0f - alpha;

    float d0 = 0.f, d1 = 0.f, d2 = 0.f, d3 = 0.f, m = 0.f, s = 0.f;
    const int st = HB_ / 4;
    const float4* U4 = (const float4*)U + (size_t)b * T_ * st + h;
    __half* Sp  = S  + (size_t)b * T_ * H_ + h;
    __half* Ssp = Ss + (size_t)b * T_ * H_ + h;

    float4 buf[8];
#pragma unroll
    for (int i = 0; i < 8; i++) buf[i] = U4[(size_t)i * st];

    for (int t0 = 0; t0 < 256; t0 += 8) {
#pragma unroll
        for (int i = 0; i < 8; i++) {
            const int t = t0 + i;
            const float4 u = buf[i];
            const int tp = (t + 8 < T_) ? (t + 8) : (T_ - 1);
            buf[i] = U4[(size_t)tp * st];

            d0 = beta[0] * d0 + ob[0] * (u.x + bb[0]);
            d1 = beta[1] * d1 + ob[1] * (u.y + bb[1]);
            d2 = beta[2] * d2 + ob[2] * (u.z + bb[2]);
            d3 = beta[3] * d3 + ob[3] * (u.w + bb[3]);

            m = m * alpha + oa * (d0 + d1 + d2 + d3) - s;  // VTH=1, DT=1
            s = (m > 1.0f) ? 1.0f : 0.0f;
            if (t < T_) {
                Sp[(size_t)t * H_] = __float2half_rn(s);
                if (TWO) Ssp[(size_t)t * H_] = __float2half_rn(s * (1.0f / 2048.0f));
            }
        }
    }
}

// ---------------------------------------------------------------------------
// GEMM3: Z[M_][20] = S2[M_][512](fp16) * Wo[20][512]^T.  One warp per row.
// ---------------------------------------------------------------------------
__global__ __launch_bounds__(256)
void gemm3_kernel(const __half* __restrict__ S2, const float* __restrict__ Wo,
                  float* __restrict__ Z) {
    __shared__ float Wos[OUT_ * H_];   // 40 KB
    const int tid = threadIdx.x;
    for (int i = tid; i < OUT_ * H_; i += 256) Wos[i] = Wo[i];
    __syncthreads();

    const int warp = tid >> 5, lane = tid & 31;
    const int m = blockIdx.x * 8 + warp;

    const __half* row = S2 + (size_t)m * H_;
    float r[16];
#pragma unroll
    for (int i = 0; i < 16; i++) r[i] = __half2float(row[lane + 32 * i]);

    for (int o = 0; o < OUT_; o++) {
        float p = 0.0f;
#pragma unroll
        for (int i = 0; i < 16; i++) p += r[i] * Wos[o * H_ + lane + 32 * i];
#pragma unroll
        for (int off = 16; off > 0; off >>= 1)
            p += __shfl_xor_sync(0xffffffffu, p, off);
        if (lane == 0) Z[(size_t)m * OUT_ + o] = p;
    }
}

// ---------------------------------------------------------------------------
// Readout: leaky integrator + per-step softmax summed over t >= 11.
// ---------------------------------------------------------------------------
__global__ __launch_bounds__(32)
void readout_kernel(const float* __restrict__ Z, const float* __restrict__ bo,
                    const float* __restrict__ tau_mo, float* __restrict__ out) {
    const int b = blockIdx.x;
    const int o = threadIdx.x;
    const bool act = (o < OUT_);

    const float ao = act ? 1.0f / (1.0f + expf(-tau_mo[o])) : 0.0f;
    const float oa = 1.0f - ao;
    const float bb = act ? bo[o] : 0.0f;

    float mo = 0.0f, acc = 0.0f;
    for (int t = 0; t < T_; t++) {
        const float z = act ? Z[((size_t)b * T_ + t) * OUT_ + o] : 0.0f;
        if (act) mo = mo * ao + oa * (z + bb);

        float v = act ? mo : -3.4e38f;
#pragma unroll
        for (int off = 16; off > 0; off >>= 1)
            v = fmaxf(v, __shfl_xor_sync(0xffffffffu, v, off));

        float e = act ? expf(mo - v) : 0.0f;
        float se = e;
#pragma unroll
        for (int off = 16; off > 0; off >>= 1)
            se += __shfl_xor_sync(0xffffffffu, se, off);

        if (act && t >= WARM_) acc += e / se;
    }
    if (act) out[(size_t)b * OUT_ + o] = acc;
}

// ---------------------------------------------------------------------------
// Launch
// ---------------------------------------------------------------------------
extern "C" void kernel_launch(void* const* d_in, const int* in_sizes, int n_in,
                              void* d_out, int out_size) {
    const float* x     = (const float*)d_in[0];
    const float* W1    = (const float*)d_in[1];
    const float* b1    = (const float*)d_in[2];
    const float* tm1   = (const float*)d_in[3];
    const float* tn1   = (const float*)d_in[4];
    const float* mask1 = (const float*)d_in[5];
    const float* W2    = (const float*)d_in[6];
    const float* b2    = (const float*)d_in[7];
    const float* tm2   = (const float*)d_in[8];
    const float* tn2   = (const float*)d_in[9];
    const float* mask2 = (const float*)d_in[10];
    const float* Wo    = (const float*)d_in[11];
    const float* bo    = (const float*)d_in[12];
    const float* tmo   = (const float*)d_in[13];
    float* out = (float*)d_out;

    __half *pX, *pW1s, *pW2s, *pS1, *pS2;
    float *pU, *pZ;
    cudaGetSymbolAddress((void**)&pX,   g_Xs);
    cudaGetSymbolAddress((void**)&pW1s, g_W1s);
    cudaGetSymbolAddress((void**)&pW2s, g_W2s);
    cudaGetSymbolAddress((void**)&pU,   g_U);
    cudaGetSymbolAddress((void**)&pS1,  g_S1);
    cudaGetSymbolAddress((void**)&pS2,  g_S2);
    cudaGetSymbolAddress((void**)&pZ,   g_Z);

    const size_t PX  = (size_t)M_ * INP_;
    const size_t PW1 = (size_t)HB_ * INP_;
    const size_t PW2 = (size_t)HB_ * H_;
    const size_t PS  = (size_t)M_ * H_;

    const int SMEM0 = 2 * 5 * TBYTES;   // 102400 B (2 stages x 5 tiles)
    const int SMEM1 = 2 * 4 * TBYTES;   //  81920 B (2 stages x 4 tiles)
    cudaFuncSetAttribute(gemm_mma<0>, cudaFuncAttributeMaxDynamicSharedMemorySize, SMEM0);
    cudaFuncSetAttribute(gemm_mma<1>, cudaFuncAttributeMaxDynamicSharedMemorySize, SMEM1);

    // 1. Prep: scaled fp16 splits
    split_x_kernel <<<(unsigned)(((size_t)M_ * INP_) / 256), 256>>>(x);
    split_w1_kernel<<<(unsigned)(((size_t)HB_ * INP_) / 256), 256>>>(W1, mask1);
    split_w2_kernel<<<(unsigned)(((size_t)HB_ * H_) / 256), 256>>>(W2, mask2);

    // 2. Layer 1: U = X @ Wm1^T (3 products), scan -> S1 {s, s*2^-11}
    {
        dim3 grid(HB_ / 128, M_ / 128);
        gemm_mma<0><<<grid, 128, SMEM0>>>(pX, pX + PX, pX + 2 * PX,
                                          pW1s, pW1s + PW1, pU, INP_);
    }
    scan_kernel<1><<<(B_ * H_) / 128, 128>>>(pU, tm1, tn1, b1, pS1, pS1 + PS);

    // 3. Layer 2: U = S1 @ Wm2^T (2 products), scan -> S2
    {
        dim3 grid(HB_ / 128, M_ / 128);
        gemm_mma<1><<<grid, 128, SMEM1>>>(pS1, pS1 + PS, pS1,
                                          pW2s, pW2s + PW2, pU, H_);
    }
    scan_kernel<0><<<(B_ * H_) / 128, 128>>>(pU, tm2, tn2, b2, pS2, pS2);

    // 4. Readout
    gemm3_kernel<<<M_ / 8, 256>>>(pS2, Wo, pZ);
    readout_kernel<<<B_, 32>>>(pZ, bo, tmo, out);
}

// round 9
// speedup vs baseline: 1.6982x; 1.6982x over previous
#include <cuda_runtime.h>
#include <cuda_fp16.h>
#include <math.h>
#include <stdint.h>

// ---------------------------------------------------------------------------
// DH-SFNN forward via mma.sync fp16 scaled-split GEMMs (fp32-equivalent).
// R9 = R7 base (best: 1571us) with plane-count reduction:
//   GEMM1: U = xh*wh + xl*wh + xh*wl      [3 products, 2 A-planes, 2 B-planes]
//   GEMM2: U = s*wh + s*wl                [2 products, 1 A-plane,  2 B-planes]
// wl is stored UNSCALED (fp16 subnormal) — R7 empirically proved this mma
// path handles fp16 subnormal inputs exactly (bit-identical rel_err with
// subnormal xl inputs). Fewer tiles/chunk -> less cp.async + LDSM per chunk.
// GEMM2 gets a 3-stage cp.async pipeline (smem now fits).
// ---------------------------------------------------------------------------

#define B_    128
#define T_    250
#define IN_   700
#define INP_  704
#define H_    512
#define BR_   4
#define HB_   2048
#define OUT_  20
#define M_    (B_ * T_)    // 32000
#define WARM_ 11

// ---------------- scratch (static device globals) --------------------------
__device__ __half g_Xs [(size_t)2 * M_ * INP_];   // {xh, xl}       90 MB
__device__ __half g_W1s[(size_t)2 * HB_ * INP_];  // {wh, wl}       5.8 MB
__device__ __half g_W2s[(size_t)2 * HB_ * H_];    // {wh, wl}       4.2 MB
__device__ float  g_U  [(size_t)M_ * HB_];        // drive          262 MB
__device__ __half g_S1 [(size_t)M_ * H_];         // spikes L1      32.8 MB
__device__ __half g_S2 [(size_t)M_ * H_];         // spikes L2      32.8 MB
__device__ float  g_Z  [(size_t)M_ * OUT_];

// ---------------- PTX helpers ----------------------------------------------
__device__ __forceinline__ uint32_t smem_u32(const void* p) {
    uint32_t a;
    asm("{ .reg .u64 t; cvta.to.shared.u64 t, %1; cvt.u32.u64 %0, t; }"
        : "=r"(a) : "l"(p));
    return a;
}
__device__ __forceinline__ void ldmatrix_x4(uint32_t* r, uint32_t addr) {
    asm volatile("ldmatrix.sync.aligned.m8n8.x4.shared.b16 {%0,%1,%2,%3}, [%4];"
                 : "=r"(r[0]), "=r"(r[1]), "=r"(r[2]), "=r"(r[3]) : "r"(addr));
}
__device__ __forceinline__ void mma16816(float* c, const uint32_t* a,
                                         uint32_t b0, uint32_t b1) {
    asm volatile(
        "mma.sync.aligned.m16n8k16.row.col.f32.f16.f16.f32 "
        "{%0,%1,%2,%3}, {%4,%5,%6,%7}, {%8,%9}, {%0,%1,%2,%3};"
        : "+f"(c[0]), "+f"(c[1]), "+f"(c[2]), "+f"(c[3])
        : "r"(a[0]), "r"(a[1]), "r"(a[2]), "r"(a[3]), "r"(b0), "r"(b1));
}
__device__ __forceinline__ void cp16(uint32_t dst, const void* src) {
    asm volatile("cp.async.cg.shared.global [%0], [%1], 16;"
                 :: "r"(dst), "l"(src));
}
#define CP_COMMIT() asm volatile("cp.async.commit_group;" ::: "memory")
#define CP_WAIT(n)  asm volatile("cp.async.wait_group %0;" :: "n"(n) : "memory")

// ---------------- prep kernels ---------------------------------------------
__global__ void split_x_kernel(const float* __restrict__ x) {
    size_t idx = (size_t)blockIdx.x * blockDim.x + threadIdx.x;
    if (idx >= (size_t)M_ * INP_) return;
    int mm = (int)(idx / INP_), c = (int)(idx % INP_);
    float v = (c < IN_) ? x[(size_t)mm * IN_ + c] : 0.0f;
    __half h = __float2half_rn(v);
    __half l = __float2half_rn(v - __half2float(h));
    const size_t P = (size_t)M_ * INP_;
    g_Xs[idx] = h; g_Xs[P + idx] = l;
}

__global__ void split_w1_kernel(const float* __restrict__ W1,
                                const float* __restrict__ mask1) {
    size_t idx = (size_t)blockIdx.x * blockDim.x + threadIdx.x;
    if (idx >= (size_t)HB_ * INP_) return;
    int r = (int)(idx / INP_), c = (int)(idx % INP_);
    float v = (c < IN_) ? W1[(size_t)r * IN_ + c] * mask1[(size_t)r * IN_ + c] : 0.0f;
    __half h = __float2half_rn(v);
    __half l = __float2half_rn(v - __half2float(h));   // subnormal fp16, exact-enough
    const size_t P = (size_t)HB_ * INP_;
    g_W1s[idx] = h; g_W1s[P + idx] = l;
}

__global__ void split_w2_kernel(const float* __restrict__ W2,
                                const float* __restrict__ mask2) {
    size_t idx = (size_t)blockIdx.x * blockDim.x + threadIdx.x;
    if (idx >= (size_t)HB_ * H_) return;
    float v = W2[idx] * mask2[idx];
    __half h = __float2half_rn(v);
    __half l = __float2half_rn(v - __half2float(h));
    const size_t P = (size_t)HB_ * H_;
    g_W2s[idx] = h; g_W2s[P + idx] = l;
}

// ---------------------------------------------------------------------------
// fp16 mma.sync GEMM:  U[128m x 128n] = sum_p A[pa]*B[pb]^T
// CTA 128x128, 8 warps (2m x 4n), warp tile 64x32, K-chunk 32.  (R7 shape)
// MODE 0: A {xh, xl}, B {wh, wl}; products (xh,wh),(xl,wh),(xh,wl). 2-stage.
// MODE 1: A {s},      B {wh, wl}; products (s,wh),(s,wl).          3-stage.
// Fragment reuse in-order: B frags reused across consecutive A-plane products,
// A frags reused across consecutive B-plane products (no extra registers).
// ---------------------------------------------------------------------------
#define TSTRIDE 40
#define TBYTES  (128 * TSTRIDE * 2)      // 10240 B per tile

template <int MODE>
__global__ __launch_bounds__(256, 2)
void gemm_mma(const __half* __restrict__ A0, const __half* __restrict__ A1,
              const __half* __restrict__ Bw0, const __half* __restrict__ Bw1,
              float* __restrict__ U, int K)
{
    constexpr int NA   = (MODE == 0) ? 2 : 1;
    constexpr int NT   = NA + 2;
    constexpr int NSTG = (MODE == 0) ? 2 : 3;
    constexpr int STG  = NT * TBYTES;    // stage stride in bytes

    extern __shared__ char smem[];
    const uint32_t sb = smem_u32(smem);

    const int tid  = threadIdx.x;
    const int wid  = tid >> 5, lane = tid & 31;
    const int m0   = blockIdx.y * 128, n0 = blockIdx.x * 128;
    const int mw   = (wid >> 2) * 64;
    const int nw   = (wid & 3) * 32;

    const int a_row = lane & 15;
    const int a_kh  = (lane >> 4) << 3;
    const int b_n   = (lane & 7) + ((lane >> 4) << 3);
    const int b_kh  = ((lane >> 3) & 1) << 3;

    // tile source base pointers (row 0, k 0)
    const __half* tp[NT];
    tp[0] = A0 + (size_t)m0 * K;
    if (MODE == 0) tp[1] = A1 + (size_t)m0 * K;
    tp[NA]     = Bw0 + (size_t)n0 * K;
    tp[NA + 1] = Bw1 + (size_t)n0 * K;

    // per-thread load coords: 2 x 16B per tile (512 quads / 256 threads)
    const int lq = tid & 3;            // 16B quad in row
    const int lr = tid >> 2;           // row 0..63 (+64 on second pass)

    float acc[4][4][4];
#pragma unroll
    for (int i = 0; i < 4; i++)
#pragma unroll
        for (int j = 0; j < 4; j++)
#pragma unroll
            for (int q = 0; q < 4; q++) acc[i][j][q] = 0.0f;

    const int nchunk = K >> 5;

    // ---- prologue: fill NSTG-1 stages ----
#pragma unroll
    for (int s = 0; s < NSTG - 1; s++) {
        const int k0 = s << 5;
#pragma unroll
        for (int t = 0; t < NT; t++)
#pragma unroll
            for (int j = 0; j < 2; j++) {
                const int r = lr + j * 64;
                cp16(sb + s * STG + t * TBYTES + (r * TSTRIDE + lq * 8) * 2,
                     tp[t] + (size_t)r * K + k0 + lq * 8);
            }
        CP_COMMIT();
    }

    for (int ch = 0; ch < nchunk; ch++) {
        CP_WAIT(NSTG - 2);
        __syncthreads();   // stage ch%NSTG ready; all warps past its last use

        // issue loads for chunk ch+NSTG-1 (overlaps MMAs below)
        if (ch + NSTG - 1 < nchunk) {
            const int k1 = (ch + NSTG - 1) << 5;
            const uint32_t so = ((ch + NSTG - 1) % NSTG) * STG;
#pragma unroll
            for (int t = 0; t < NT; t++)
#pragma unroll
                for (int j = 0; j < 2; j++) {
                    const int r = lr + j * 64;
                    cp16(sb + so + t * TBYTES + (r * TSTRIDE + lq * 8) * 2,
                         tp[t] + (size_t)r * K + k1 + lq * 8);
                }
        }
        CP_COMMIT();

        // ---- MMA on stage ch%NSTG ----
        const uint32_t cb = sb + (ch % NSTG) * STG;
#pragma unroll
        for (int kt = 0; kt < 2; kt++) {
            uint32_t af[4], bf[2][4];

            // helper lambdas (inlined): load A plane pl / B plane pl
            #define LDA(pl)                                                     \
                _Pragma("unroll")                                               \
                for (int mi = 0; mi < 4; mi++)                                  \
                    ldmatrix_x4(af + 0, cb); /* placeholder (unused) */
            #undef LDA

#pragma unroll
            for (int dummy = 0; dummy < 1; dummy++) {
                // --- product 1: (A0, B0) ---
                uint32_t afl[4][4];
#pragma unroll
                for (int mi = 0; mi < 4; mi++)
                    ldmatrix_x4(afl[mi],
                        cb + 0 * TBYTES
                           + 2u * (uint32_t)((mw + mi * 16 + a_row) * TSTRIDE
                                             + kt * 16 + a_kh));
#pragma unroll
                for (int ng = 0; ng < 2; ng++)
                    ldmatrix_x4(bf[ng],
                        cb + NA * TBYTES
                           + 2u * (uint32_t)((nw + ng * 16 + b_n) * TSTRIDE
                                             + kt * 16 + b_kh));
#pragma unroll
                for (int mi = 0; mi < 4; mi++)
#pragma unroll
                    for (int ni = 0; ni < 4; ni++)
                        mma16816(acc[mi][ni], afl[mi],
                                 bf[ni >> 1][(ni & 1) * 2],
                                 bf[ni >> 1][(ni & 1) * 2 + 1]);

                if (MODE == 0) {
                    // --- product 2: (A1, B0) — reuse bf ---
#pragma unroll
                    for (int mi = 0; mi < 4; mi++)
                        ldmatrix_x4(afl[mi],
                            cb + 1 * TBYTES
                               + 2u * (uint32_t)((mw + mi * 16 + a_row) * TSTRIDE
                                                 + kt * 16 + a_kh));
#pragma unroll
                    for (int mi = 0; mi < 4; mi++)
#pragma unroll
                        for (int ni = 0; ni < 4; ni++)
                            mma16816(acc[mi][ni], afl[mi],
                                     bf[ni >> 1][(ni & 1) * 2],
                                     bf[ni >> 1][(ni & 1) * 2 + 1]);
                    // --- product 3: (A0, B1) — reload A0, new B ---
#pragma unroll
                    for (int mi = 0; mi < 4; mi++)
                        ldmatrix_x4(afl[mi],
                            cb + 0 * TBYTES
                               + 2u * (uint32_t)((mw + mi * 16 + a_row) * TSTRIDE
                                                 + kt * 16 + a_kh));
                }
                // B plane 1 (both modes; MODE1 reuses af from product 1)
#pragma unroll
                for (int ng = 0; ng < 2; ng++)
                    ldmatrix_x4(bf[ng],
                        cb + (NA + 1) * TBYTES
                           + 2u * (uint32_t)((nw + ng * 16 + b_n) * TSTRIDE
                                             + kt * 16 + b_kh));
#pragma unroll
                for (int mi = 0; mi < 4; mi++)
#pragma unroll
                    for (int ni = 0; ni < 4; ni++)
                        mma16816(acc[mi][ni], afl[mi],
                                 bf[ni >> 1][(ni & 1) * 2],
                                 bf[ni >> 1][(ni & 1) * 2 + 1]);
            }
        }
    }

    // Epilogue: direct global stores (float2), C frag layout m16n8.f32
    const int er = lane >> 2;
    const int ec = (lane & 3) * 2;
#pragma unroll
    for (int mi = 0; mi < 4; mi++) {
#pragma unroll
        for (int ni = 0; ni < 4; ni++) {
            const size_t row = (size_t)(m0 + mw + mi * 16 + er);
            const size_t col = (size_t)(n0 + nw + ni * 8 + ec);
            *(float2*)&U[row * HB_ + col] =
                make_float2(acc[mi][ni][0], acc[mi][ni][1]);
            *(float2*)&U[(row + 8) * HB_ + col] =
                make_float2(acc[mi][ni][2], acc[mi][ni][3]);
        }
    }
}

// ---------------------------------------------------------------------------
// LIF scan (fp32 state, fp16 spike output — spikes 0/1 exact).
// 8-deep prefetch pipeline for MLP.
// ---------------------------------------------------------------------------
__global__ __launch_bounds__(128)
void scan_kernel(const float* __restrict__ U, const float* __restrict__ tau_m,
                 const float* __restrict__ tau_n, const float* __restrict__ bias,
                 __half* __restrict__ S)
{
    const int idx = blockIdx.x * blockDim.x + threadIdx.x;
    const int b = idx >> 9, h = idx & 511;

    float beta[4], ob[4], bb[4];
#pragma unroll
    for (int j = 0; j < 4; j++) {
        const float tn = tau_n[h * 4 + j];
        beta[j] = 1.0f / (1.0f + expf(-tn));
        ob[j]   = 1.0f - beta[j];
        bb[j]   = bias[h * 4 + j];
    }
    const float alpha = 1.0f / (1.0f + expf(-tau_m[h]));
    const float oa    = 1.0f - alpha;

    float d0 = 0.f, d1 = 0.f, d2 = 0.f, d3 = 0.f, m = 0.f, s = 0.f;
    const int st = HB_ / 4;
    const float4* U4 = (const float4*)U + (size_t)b * T_ * st + h;
    __half* Sp = S + (size_t)b * T_ * H_ + h;

    float4 buf[8];
#pragma unroll
    for (int i = 0; i < 8; i++) buf[i] = U4[(size_t)i * st];

    for (int t0 = 0; t0 < 256; t0 += 8) {
#pragma unroll
        for (int i = 0; i < 8; i++) {
            const int t = t0 + i;
            const float4 u = buf[i];
            const int tp = (t + 8 < T_) ? (t + 8) : (T_ - 1);
            buf[i] = U4[(size_t)tp * st];

            d0 = beta[0] * d0 + ob[0] * (u.x + bb[0]);
            d1 = beta[1] * d1 + ob[1] * (u.y + bb[1]);
            d2 = beta[2] * d2 + ob[2] * (u.z + bb[2]);
            d3 = beta[3] * d3 + ob[3] * (u.w + bb[3]);

            m = m * alpha + oa * (d0 + d1 + d2 + d3) - s;  // VTH=1, DT=1
            s = (m > 1.0f) ? 1.0f : 0.0f;
            if (t < T_) Sp[(size_t)t * H_] = __float2half_rn(s);
        }
    }
}

// ---------------------------------------------------------------------------
// GEMM3: Z[M_][20] = S2[M_][512](fp16) * Wo[20][512]^T.  One warp per row.
// ---------------------------------------------------------------------------
__global__ __launch_bounds__(256)
void gemm3_kernel(const __half* __restrict__ S2, const float* __restrict__ Wo,
                  float* __restrict__ Z) {
    __shared__ float Wos[OUT_ * H_];   // 40 KB
    const int tid = threadIdx.x;
    for (int i = tid; i < OUT_ * H_; i += 256) Wos[i] = Wo[i];
    __syncthreads();

    const int warp = tid >> 5, lane = tid & 31;
    const int m = blockIdx.x * 8 + warp;

    const __half* row = S2 + (size_t)m * H_;
    float r[16];
#pragma unroll
    for (int i = 0; i < 16; i++) r[i] = __half2float(row[lane + 32 * i]);

    for (int o = 0; o < OUT_; o++) {
        float p = 0.0f;
#pragma unroll
        for (int i = 0; i < 16; i++) p += r[i] * Wos[o * H_ + lane + 32 * i];
#pragma unroll
        for (int off = 16; off > 0; off >>= 1)
            p += __shfl_xor_sync(0xffffffffu, p, off);
        if (lane == 0) Z[(size_t)m * OUT_ + o] = p;
    }
}

// ---------------------------------------------------------------------------
// Readout: leaky integrator + per-step softmax summed over t >= 11.
// ---------------------------------------------------------------------------
__global__ __launch_bounds__(32)
void readout_kernel(const float* __restrict__ Z, const float* __restrict__ bo,
                    const float* __restrict__ tau_mo, float* __restrict__ out) {
    const int b = blockIdx.x;
    const int o = threadIdx.x;
    const bool act = (o < OUT_);

    const float ao = act ? 1.0f / (1.0f + expf(-tau_mo[o])) : 0.0f;
    const float oa = 1.0f - ao;
    const float bb = act ? bo[o] : 0.0f;

    float mo = 0.0f, acc = 0.0f;
    for (int t = 0; t < T_; t++) {
        const float z = act ? Z[((size_t)b * T_ + t) * OUT_ + o] : 0.0f;
        if (act) mo = mo * ao + oa * (z + bb);

        float v = act ? mo : -3.4e38f;
#pragma unroll
        for (int off = 16; off > 0; off >>= 1)
            v = fmaxf(v, __shfl_xor_sync(0xffffffffu, v, off));

        float e = act ? expf(mo - v) : 0.0f;
        float se = e;
#pragma unroll
        for (int off = 16; off > 0; off >>= 1)
            se += __shfl_xor_sync(0xffffffffu, se, off);

        if (act && t >= WARM_) acc += e / se;
    }
    if (act) out[(size_t)b * OUT_ + o] = acc;
}

// ---------------------------------------------------------------------------
// Launch
// ---------------------------------------------------------------------------
extern "C" void kernel_launch(void* const* d_in, const int* in_sizes, int n_in,
                              void* d_out, int out_size) {
    const float* x     = (const float*)d_in[0];
    const float* W1    = (const float*)d_in[1];
    const float* b1    = (const float*)d_in[2];
    const float* tm1   = (const float*)d_in[3];
    const float* tn1   = (const float*)d_in[4];
    const float* mask1 = (const float*)d_in[5];
    const float* W2    = (const float*)d_in[6];
    const float* b2    = (const float*)d_in[7];
    const float* tm2   = (const float*)d_in[8];
    const float* tn2   = (const float*)d_in[9];
    const float* mask2 = (const float*)d_in[10];
    const float* Wo    = (const float*)d_in[11];
    const float* bo    = (const float*)d_in[12];
    const float* tmo   = (const float*)d_in[13];
    float* out = (float*)d_out;

    __half *pX, *pW1s, *pW2s, *pS1, *pS2;
    float *pU, *pZ;
    cudaGetSymbolAddress((void**)&pX,   g_Xs);
    cudaGetSymbolAddress((void**)&pW1s, g_W1s);
    cudaGetSymbolAddress((void**)&pW2s, g_W2s);
    cudaGetSymbolAddress((void**)&pU,   g_U);
    cudaGetSymbolAddress((void**)&pS1,  g_S1);
    cudaGetSymbolAddress((void**)&pS2,  g_S2);
    cudaGetSymbolAddress((void**)&pZ,   g_Z);

    const size_t PX  = (size_t)M_ * INP_;
    const size_t PW1 = (size_t)HB_ * INP_;
    const size_t PW2 = (size_t)HB_ * H_;

    const int SMEM0 = 2 * 4 * TBYTES;   // 81920 B (2 stages x 4 tiles)
    const int SMEM1 = 3 * 3 * TBYTES;   // 92160 B (3 stages x 3 tiles)
    cudaFuncSetAttribute(gemm_mma<0>, cudaFuncAttributeMaxDynamicSharedMemorySize, SMEM0);
    cudaFuncSetAttribute(gemm_mma<1>, cudaFuncAttributeMaxDynamicSharedMemorySize, SMEM1);

    // 1. Prep: fp16 splits {hi, lo} (lo subnormal for weights — exact in mma)
    split_x_kernel <<<(unsigned)(((size_t)M_ * INP_) / 256), 256>>>(x);
    split_w1_kernel<<<(unsigned)(((size_t)HB_ * INP_) / 256), 256>>>(W1, mask1);
    split_w2_kernel<<<(unsigned)(((size_t)HB_ * H_) / 256), 256>>>(W2, mask2);

    // 2. Layer 1: U = X @ Wm1^T (3 products), scan -> S1
    {
        dim3 grid(HB_ / 128, M_ / 128);
        gemm_mma<0><<<grid, 256, SMEM0>>>(pX, pX + PX, pW1s, pW1s + PW1, pU, INP_);
    }
    scan_kernel<<<(B_ * H_) / 128, 128>>>(pU, tm1, tn1, b1, pS1);

    // 3. Layer 2: U = S1 @ Wm2^T (2 products), scan -> S2
    {
        dim3 grid(HB_ / 128, M_ / 128);
        gemm_mma<1><<<grid, 256, SMEM1>>>(pS1, pS1, pW2s, pW2s + PW2, pU, H_);
    }
    scan_kernel<<<(B_ * H_) / 128, 128>>>(pU, tm2, tn2, b2, pS2);

    // 4. Readout
    gemm3_kernel<<<M_ / 8, 256>>>(pS2, Wo, pZ);
    readout_kernel<<<B_, 32>>>(pZ, bo, tmo, out);
}